// round 16
// baseline (speedup 1.0000x reference)
#include <cuda_runtime.h>
#include <cuda_fp16.h>
#include <cstdint>
#include <math.h>

#define S_LEN 4096
#define DMODEL 768
#define NHEADS 12
#define DHEAD 64

// Scratch (static device globals — no allocation allowed)
__device__ __half g_Qh[NHEADS * S_LEN * DHEAD];   // [h][s][d] fp16(0.125*log2e*qproj)
__device__ __half g_Kh[NHEADS * S_LEN * DHEAD];   // [h][s][d] fp16
__device__ __half g_Vh[NHEADS * S_LEN * DHEAD];   // [h][s][d] fp16 (natural)
__device__ __half g_Ctx[S_LEN * DMODEL];          // [s][dmodel] fp16
// fp16 copies of inputs/weights
__device__ __half g_Aq[S_LEN * DMODEL];
__device__ __half g_Ak[S_LEN * DMODEL];
__device__ __half g_Av[S_LEN * DMODEL];
__device__ __half g_Wq[DMODEL * DMODEL];
__device__ __half g_Wk[DMODEL * DMODEL];
__device__ __half g_Wv[DMODEL * DMODEL];
__device__ __half g_Wo[DMODEL * DMODEL];

#define QSCALE 0.1803368801111214f   // 0.125 * log2(e)

// ---------------------------------------------------------------------------
// PTX helpers (sm_80-era PTX only — compute_103 baseline-safe)
// ---------------------------------------------------------------------------
__device__ __forceinline__ uint32_t smem_u32(const void* p) {
    uint32_t a;
    asm("{ .reg .u64 t; cvta.to.shared.u64 t, %1; cvt.u32.u64 %0, t; }"
        : "=r"(a) : "l"(p));
    return a;
}

#define CP_ASYNC16(dst, src) \
    asm volatile("cp.async.cg.shared.global [%0], [%1], 16;" \
                 :: "r"(dst), "l"(src))
#define CP_COMMIT() asm volatile("cp.async.commit_group;" ::: "memory")
#define CP_WAIT3()  asm volatile("cp.async.wait_group 3;" ::: "memory")
#define CP_WAIT2()  asm volatile("cp.async.wait_group 2;" ::: "memory")
#define CP_WAIT1()  asm volatile("cp.async.wait_group 1;" ::: "memory")
#define CP_WAIT0()  asm volatile("cp.async.wait_group 0;" ::: "memory")

__device__ __forceinline__ void ldsm_x4(uint32_t* r, uint32_t addr) {
    asm volatile("ldmatrix.sync.aligned.m8n8.x4.shared.b16 {%0,%1,%2,%3}, [%4];"
                 : "=r"(r[0]), "=r"(r[1]), "=r"(r[2]), "=r"(r[3]) : "r"(addr));
}
__device__ __forceinline__ void ldsm_x4t(uint32_t* r, uint32_t addr) {
    asm volatile("ldmatrix.sync.aligned.m8n8.x4.trans.shared.b16 {%0,%1,%2,%3}, [%4];"
                 : "=r"(r[0]), "=r"(r[1]), "=r"(r[2]), "=r"(r[3]) : "r"(addr));
}
__device__ __forceinline__ void mma_f16(float* c, const uint32_t* a, const uint32_t* b) {
    asm volatile(
        "mma.sync.aligned.m16n8k16.row.col.f32.f16.f16.f32 "
        "{%0,%1,%2,%3}, {%4,%5,%6,%7}, {%8,%9}, {%0,%1,%2,%3};"
        : "+f"(c[0]), "+f"(c[1]), "+f"(c[2]), "+f"(c[3])
        : "r"(a[0]), "r"(a[1]), "r"(a[2]), "r"(a[3]), "r"(b[0]), "r"(b[1]));
}
__device__ __forceinline__ uint32_t packh2(float x, float y) {
    __half2 h = __floats2half2_rn(x, y);
    return *(uint32_t*)&h;
}
__device__ __forceinline__ uint32_t h2exp2u(uint32_t x) {
    uint32_t r;
    asm("ex2.approx.f16x2 %0, %1;" : "=r"(r) : "r"(x));
    return r;
}

// ---------------------------------------------------------------------------
// Pre-convert pass: f32 -> f16 for inputs and weights (memory bound)
// ---------------------------------------------------------------------------
#define NA8 (S_LEN * DMODEL / 8)
#define NW8 (DMODEL * DMODEL / 8)
#define PRE_TOTAL (3 * NA8 + 4 * NW8)

__global__ __launch_bounds__(256)
void round_pre(const float* __restrict__ q, const float* __restrict__ k,
               const float* __restrict__ v,
               const float* __restrict__ wq, const float* __restrict__ wk,
               const float* __restrict__ wv, const float* __restrict__ wo)
{
    int idx = blockIdx.x * 256 + threadIdx.x;
    if (idx >= PRE_TOTAL) return;
    const float* src;
    __half* dst;
    int local;
    if (idx < 3 * NA8) {
        int t = idx / NA8;
        local = idx - t * NA8;
        src = (t == 0) ? q : (t == 1) ? k : v;
        dst = (t == 0) ? g_Aq : (t == 1) ? g_Ak : g_Av;
    } else {
        int j = idx - 3 * NA8;
        int t = j / NW8;
        local = j - t * NW8;
        src = (t == 0) ? wq : (t == 1) ? wk : (t == 2) ? wv : wo;
        dst = (t == 0) ? g_Wq : (t == 1) ? g_Wk : (t == 2) ? g_Wv : g_Wo;
    }
    const float4* s4 = (const float4*)src + local * 2;
    float4 x0 = s4[0], x1 = s4[1];
    uint4 o;
    o.x = packh2(x0.x, x0.y);
    o.y = packh2(x0.z, x0.w);
    o.z = packh2(x1.x, x1.y);
    o.w = packh2(x1.z, x1.w);
    ((uint4*)dst)[local] = o;
}

// ---------------------------------------------------------------------------
// FP16 GEMM 64x128 tile core: BK=32, 24 k-tiles, 256 threads, 8 warps of
// 64m x 16n. Rows padded to 80B. THREE-stage cp.async (45KB smem; with max
// carveout -> up to 5 CTAs/SM), 1 barrier/tile.
// ---------------------------------------------------------------------------
#define ROWB 80
#define B_TILE_BYTES (128 * ROWB)
#define A_TILE_BYTES (64 * ROWB)
#define G_STAGE_BYTES (A_TILE_BYTES + B_TILE_BYTES)   // 15360
#define NSTAGE 3
#define GEMM_SMEM_BYTES (NSTAGE * G_STAGE_BYTES)      // 46080
#define KT_TILES 24

#define GEMM64_CORE(A_PTR, B_PTR, ACC)                                         \
    extern __shared__ float sm[];                                              \
    const uint32_t sbase = smem_u32(sm);                                       \
    const int tid  = threadIdx.x;                                              \
    const int lane = tid & 31;                                                 \
    const int wid  = tid >> 5;                                                 \
    const int warp_n = wid * 16;                                               \
    const char* gA = (const char*)(A_PTR);                                     \
    const char* gB = (const char*)(B_PTR);                                     \
    auto issue = [&](int kt, int stage) {                                      \
        uint32_t dstBase = sbase + stage * G_STAGE_BYTES;                      \
        _Pragma("unroll")                                                      \
        for (int c = 0; c < 3; c++) {                                          \
            int idx = tid + c * 256;                                           \
            if (idx < 256) {                                                   \
                int row = idx >> 2, ch = idx & 3;                              \
                CP_ASYNC16(dstBase + row * ROWB + ch * 16,                     \
                           gA + (size_t)row * 1536 + (size_t)kt * 64 + ch * 16); \
            } else {                                                           \
                int j = idx - 256;                                             \
                int row = j >> 2, ch = j & 3;                                  \
                CP_ASYNC16(dstBase + A_TILE_BYTES + row * ROWB + ch * 16,      \
                           gB + (size_t)row * 1536 + (size_t)kt * 64 + ch * 16); \
            }                                                                  \
        }                                                                      \
    };                                                                         \
    _Pragma("unroll")                                                          \
    for (int i = 0; i < 4; i++)                                                \
        _Pragma("unroll")                                                      \
        for (int j = 0; j < 2; j++)                                            \
            _Pragma("unroll")                                                  \
            for (int r = 0; r < 4; r++) ACC[i][j][r] = 0.f;                    \
    issue(0, 0); CP_COMMIT();                                                  \
    issue(1, 1); CP_COMMIT();                                                  \
    const int a_row  = lane & 15;                                              \
    const int a_ch   = (lane >> 4) & 1;                                        \
    const int b_row  = lane & 7;                                               \
    const int b_half = (lane >> 3) & 1;                                        \
    const int b_pair = (lane >> 4) & 1;                                        \
    int st_cur = 0, st_nxt = 2;                                                \
    for (int kt = 0; kt < KT_TILES; kt++) {                                    \
        CP_WAIT1();                                                            \
        __syncthreads();                                                       \
        if (kt + 2 < KT_TILES) issue(kt + 2, st_nxt);                          \
        CP_COMMIT();                                                           \
        uint32_t aS = sbase + st_cur * G_STAGE_BYTES;                          \
        uint32_t bS = aS + A_TILE_BYTES;                                       \
        _Pragma("unroll")                                                      \
        for (int ks = 0; ks < 2; ks++) {                                       \
            uint32_t a[4][4], b[2][2];                                         \
            _Pragma("unroll")                                                  \
            for (int am = 0; am < 4; am++)                                     \
                ldsm_x4(a[am], aS + (am * 16 + a_row) * ROWB + ks * 32 + a_ch * 16); \
            {                                                                  \
                uint32_t t4[4];                                                \
                ldsm_x4(t4, bS + (warp_n + b_pair * 8 + b_row) * ROWB          \
                            + ks * 32 + b_half * 16);                          \
                b[0][0] = t4[0]; b[0][1] = t4[1];                              \
                b[1][0] = t4[2]; b[1][1] = t4[3];                              \
            }                                                                  \
            _Pragma("unroll")                                                  \
            for (int am = 0; am < 4; am++)                                     \
                _Pragma("unroll")                                              \
                for (int bn = 0; bn < 2; bn++)                                 \
                    mma_f16(ACC[am][bn], a[am], b[bn]);                        \
        }                                                                      \
        st_cur = (st_cur == 2) ? 0 : st_cur + 1;                               \
        st_nxt = (st_nxt == 2) ? 0 : st_nxt + 1;                               \
    }

// Fused Q/K/V projections, 64x128 tiles. z selects projection.
__global__ __launch_bounds__(256)
void gemm_qkv(const float* __restrict__ bq, const float* __restrict__ bk,
              const float* __restrict__ bv)
{
    const int z = blockIdx.z;
    const __half* A   = (z == 0) ? g_Aq : (z == 1) ? g_Ak : g_Av;
    const __half* W   = (z == 0) ? g_Wq : (z == 1) ? g_Wk : g_Wv;
    const float* bias = (z == 0) ? bq : (z == 1) ? bk : bv;
    const int m0 = blockIdx.y * 64;
    const int n0 = blockIdx.x * 128;

    float acc[4][2][4];
    GEMM64_CORE(A + (size_t)m0 * DMODEL, W + (size_t)n0 * DMODEL, acc)

    const int g   = lane >> 2;
    const int tig = lane & 3;
#pragma unroll
    for (int am = 0; am < 4; am++) {
#pragma unroll
        for (int bn = 0; bn < 2; bn++) {
            int ncol = n0 + warp_n + bn * 8 + tig * 2;
            float2 bz = *(const float2*)(bias + ncol);
            int hd = ncol >> 6;
            int d  = ncol & 63;
            __half* base = (z == 0) ? g_Qh : (z == 1) ? g_Kh : g_Vh;
            float sc = (z == 0) ? QSCALE : 1.f;
#pragma unroll
            for (int h = 0; h < 2; h++) {
                int m = m0 + am * 16 + g + h * 8;
                float ox = (acc[am][bn][h * 2 + 0] + bz.x) * sc;
                float oy = (acc[am][bn][h * 2 + 1] + bz.y) * sc;
                *(uint32_t*)(base + ((size_t)hd * S_LEN + m) * DHEAD + d) =
                    packh2(ox, oy);
            }
        }
    }
}

// Output projection: g_Ctx (fp16) @ g_Wo^T + bo -> fp32 out.
__global__ __launch_bounds__(256)
void gemm_out(const float* __restrict__ bo, float* __restrict__ Out)
{
    const int m0 = blockIdx.y * 64;
    const int n0 = blockIdx.x * 128;

    float acc[4][2][4];
    GEMM64_CORE(g_Ctx + (size_t)m0 * DMODEL, g_Wo + (size_t)n0 * DMODEL, acc)

    const int g   = lane >> 2;
    const int tig = lane & 3;
#pragma unroll
    for (int am = 0; am < 4; am++) {
#pragma unroll
        for (int bn = 0; bn < 2; bn++) {
            int ncol = n0 + warp_n + bn * 8 + tig * 2;
            float2 bz = *(const float2*)(bo + ncol);
#pragma unroll
            for (int h = 0; h < 2; h++) {
                int m = m0 + am * 16 + g + h * 8;
                float2 o;
                o.x = acc[am][bn][h * 2 + 0] + bz.x;
                o.y = acc[am][bn][h * 2 + 1] + bz.y;
                *(float2*)(Out + (size_t)m * DMODEL + ncol) = o;
            }
        }
    }
}

// ---------------------------------------------------------------------------
// FP16 flash attention (causal) — round-14 verbatim (measured best):
// round-9 core + global LPT ordering + 4 CTAs/SM.
// ---------------------------------------------------------------------------
#define KS_ROWB 144
#define KS_STG  (64 * KS_ROWB)          // 9216
#define OFF_K0  0
#define OFF_K1  (OFF_K0 + KS_STG)
#define OFF_V0  (OFF_K1 + KS_STG)
#define OFF_V1  (OFF_V0 + KS_STG)
#define OFF_Q   (OFF_V1 + KS_STG)
#define ATTN_SMEM_BYTES (OFF_Q + KS_STG)   // 46080

__global__ __launch_bounds__(128, 4)
void flash_attn_mma()
{
    extern __shared__ char smc[];
    const uint32_t sb = smem_u32(smc);
    const int tid  = threadIdx.x;
    const int lane = tid & 31;
    const int w    = tid >> 5;
    // Global LPT ordering: biggest q-blocks first, round-robin across heads.
    const int bid  = blockIdx.x;
    const int head = bid % NHEADS;
    const int qb   = (S_LEN / 64 - 1) - (bid / NHEADS);
    const int q0   = qb * 64;

    const __half* Qg = g_Qh + (size_t)head * S_LEN * DHEAD;
    const __half* Kg = g_Kh + (size_t)head * S_LEN * DHEAD;
    const __half* Vg = g_Vh + (size_t)head * S_LEN * DHEAD;

    const int ntiles = qb + 1;

    // group 1: Q tile (64 rows x 128B)
#pragma unroll
    for (int p = 0; p < 4; p++) {
        int e   = tid + p * 128;
        int row = e >> 3;
        int ch  = e & 7;
        CP_ASYNC16(sb + OFF_Q + row * KS_ROWB + ch * 16,
                   (const char*)Qg + (size_t)(q0 + row) * 128 + ch * 16);
    }
    CP_COMMIT();

    auto issue_K = [&](int t) {
        uint32_t ksB = sb + ((t & 1) ? OFF_K1 : OFF_K0);
        int kv0 = t * 64;
#pragma unroll
        for (int c = 0; c < 4; c++) {
            int j = tid + c * 128;
            int row = j >> 3;
            int ch  = j & 7;
            CP_ASYNC16(ksB + row * KS_ROWB + ch * 16,
                       (const char*)Kg + (size_t)(kv0 + row) * 128 + ch * 16);
        }
    };
    auto issue_V = [&](int t) {
        uint32_t vB = sb + ((t & 1) ? OFF_V1 : OFF_V0);
        int kv0 = t * 64;
#pragma unroll
        for (int c = 0; c < 4; c++) {
            int j = tid + c * 128;
            int row = j >> 3;
            int ch  = j & 7;
            CP_ASYNC16(vB + row * KS_ROWB + ch * 16,
                       (const char*)Vg + (size_t)(kv0 + row) * 128 + ch * 16);
        }
    };

    issue_K(0); CP_COMMIT();                  // group 2
    if (ntiles > 1) issue_K(1);
    CP_COMMIT();                              // group 3
    issue_V(0); CP_COMMIT();                  // group 4

    CP_WAIT3();            // Q done
    __syncthreads();

    const int a_row = lane & 15;
    const int a_ch  = (lane >> 4) & 1;
    const uint32_t aQ = sb + OFF_Q + (w * 16 + a_row) * KS_ROWB + a_ch * 16;

    uint32_t qh[4][4];
#pragma unroll
    for (int kb = 0; kb < 4; kb++)
        ldsm_x4(qh[kb], aQ + kb * 32);

    float m_[2] = {-1e30f, -1e30f};
    float l_[2] = {0.f, 0.f};
    float o[8][4];
#pragma unroll
    for (int nb = 0; nb < 8; nb++)
#pragma unroll
        for (int j = 0; j < 4; j++) o[nb][j] = 0.f;

    CP_WAIT2();            // K0 done
    __syncthreads();

    const int b_nboff = ((lane >> 4) & 1) * 8;
    const int b_row   = lane & 7;
    const int b_half  = (lane >> 3) & 1;
    const int v_row   = lane & 15;
    const int v_hi    = (lane >> 4) & 1;
    const int g       = lane >> 2;
    const int tg      = lane & 3;

    // prologue: S_0 = Q K_0
    float s[8][4];
#pragma unroll
    for (int nb = 0; nb < 8; nb++)
#pragma unroll
        for (int j = 0; j < 4; j++) s[nb][j] = 0.f;
    {
        uint32_t ksS = sb + OFF_K0;
#pragma unroll
        for (int kb = 0; kb < 4; kb++) {
            uint32_t bh[16];
#pragma unroll
            for (int bp = 0; bp < 4; bp++) {
                uint32_t roff = (bp * 16 + b_nboff + b_row) * KS_ROWB + kb * 32 + b_half * 16;
                ldsm_x4(&bh[bp * 4], ksS + roff);
            }
#pragma unroll
            for (int nb = 0; nb < 8; nb++)
                mma_f16(s[nb], qh[kb], &bh[nb * 2]);
        }
    }

    for (int t = 0; t < ntiles; t++) {
        CP_WAIT0();          // K_{t+1}, V_t complete
        __syncthreads();
        if (t + 2 < ntiles) issue_K(t + 2);
        CP_COMMIT();
        if (t + 1 < ntiles) issue_V(t + 1);
        CP_COMMIT();

        const bool do_qk = (t + 1 < ntiles);
        uint32_t ksN = sb + (((t + 1) & 1) ? OFF_K1 : OFF_K0);
        uint32_t vS  = sb + ((t & 1) ? OFF_V1 : OFF_V0);

        // causal mask (diagonal tile only); scores are in log2 domain
        if (t == qb) {
            int kv0 = t * 64;
            int qa = q0 + w * 16 + g;
#pragma unroll
            for (int nb = 0; nb < 8; nb++) {
#pragma unroll
                for (int j = 0; j < 4; j++) {
                    int col = kv0 + nb * 8 + 2 * tg + (j & 1);
                    int row = qa + (j >> 1) * 8;
                    if (col > row) s[nb][j] = -1e30f;
                }
            }
        }

        // online softmax (base-2). pk[r][nb] = packed fp16 probs = PV A-frags.
        uint32_t pk[2][8];
#pragma unroll
        for (int r = 0; r < 2; r++) {
            float mx = m_[r];
#pragma unroll
            for (int nb = 0; nb < 8; nb++)
                mx = fmaxf(mx, fmaxf(s[nb][2 * r], s[nb][2 * r + 1]));
            mx = fmaxf(mx, __shfl_xor_sync(0xffffffffu, mx, 1));
            mx = fmaxf(mx, __shfl_xor_sync(0xffffffffu, mx, 2));
            float esc = exp2f(m_[r] - mx);
            float sum = 0.f;
#pragma unroll
            for (int nb = 0; nb < 8; nb++) {
                __half2 hx = __floats2half2_rn(s[nb][2 * r] - mx, s[nb][2 * r + 1] - mx);
                uint32_t pe = h2exp2u(*(uint32_t*)&hx);
                pk[r][nb] = pe;
                float2 pf = __half22float2(*(__half2*)&pe);
                sum += pf.x + pf.y;
            }
            sum += __shfl_xor_sync(0xffffffffu, sum, 1);
            sum += __shfl_xor_sync(0xffffffffu, sum, 2);
            l_[r] = l_[r] * esc + sum;
            m_[r] = mx;
#pragma unroll
            for (int nb = 0; nb < 8; nb++) {
                o[nb][2 * r]     *= esc;
                o[nb][2 * r + 1] *= esc;
            }
        }

        if (do_qk) {
#pragma unroll
            for (int nb = 0; nb < 8; nb++)
#pragma unroll
                for (int j = 0; j < 4; j++) s[nb][j] = 0.f;
        }

        // interleaved: S_{t+1} = Q K_{t+1}  +  O += P_t V_t (register P)
#pragma unroll
        for (int u = 0; u < 4; u++) {
            if (do_qk) {
                uint32_t bh[16];
#pragma unroll
                for (int bp = 0; bp < 4; bp++) {
                    uint32_t roff = (bp * 16 + b_nboff + b_row) * KS_ROWB
                                  + u * 32 + b_half * 16;
                    ldsm_x4(&bh[bp * 4], ksN + roff);
                }
#pragma unroll
                for (int nb = 0; nb < 8; nb++)
                    mma_f16(s[nb], qh[u], &bh[nb * 2]);
            }
            {
                uint32_t pa[4] = {pk[0][2 * u], pk[1][2 * u],
                                  pk[0][2 * u + 1], pk[1][2 * u + 1]};
#pragma unroll
                for (int np = 0; np < 4; np++) {
                    uint32_t t4[4];
                    ldsm_x4t(t4, vS + (u * 16 + v_row) * KS_ROWB
                                 + (2 * np + v_hi) * 16);
                    mma_f16(o[2 * np],     pa, t4);
                    mma_f16(o[2 * np + 1], pa, t4 + 2);
                }
            }
        }
    }

    // epilogue: normalize, write fp16 context [s][dmodel]
#pragma unroll
    for (int r = 0; r < 2; r++) {
        float inv = 1.f / l_[r];
        int qrow = q0 + w * 16 + g + r * 8;
        __half* dst = g_Ctx + (size_t)qrow * DMODEL + head * DHEAD + 2 * tg;
#pragma unroll
        for (int nb = 0; nb < 8; nb++) {
            *(uint32_t*)(dst + nb * 8) =
                packh2(o[nb][2 * r] * inv, o[nb][2 * r + 1] * inv);
        }
    }
}

// ---------------------------------------------------------------------------
extern "C" void kernel_launch(void* const* d_in, const int* in_sizes, int n_in,
                              void* d_out, int out_size)
{
    const float* q  = (const float*)d_in[0];
    const float* k  = (const float*)d_in[1];
    const float* v  = (const float*)d_in[2];
    const float* wq = (const float*)d_in[3];
    const float* bq = (const float*)d_in[4];
    const float* wk = (const float*)d_in[5];
    const float* bk = (const float*)d_in[6];
    const float* wv = (const float*)d_in[7];
    const float* bv = (const float*)d_in[8];
    const float* wo = (const float*)d_in[9];
    const float* bo = (const float*)d_in[10];
    float* out = (float*)d_out;

    cudaFuncSetAttribute(gemm_qkv, cudaFuncAttributeMaxDynamicSharedMemorySize, GEMM_SMEM_BYTES);
    cudaFuncSetAttribute(gemm_out, cudaFuncAttributeMaxDynamicSharedMemorySize, GEMM_SMEM_BYTES);
    cudaFuncSetAttribute(flash_attn_mma, cudaFuncAttributeMaxDynamicSharedMemorySize, ATTN_SMEM_BYTES);
    // Max shared-memory carveout: without this, the default L1/shared split
    // caps residency at ~2 CTAs/SM for 45-60KB CTAs (observed occ=31% in
    // rounds 14-15 regardless of stage count).
    cudaFuncSetAttribute(gemm_qkv, cudaFuncAttributePreferredSharedMemoryCarveout, 100);
    cudaFuncSetAttribute(gemm_out, cudaFuncAttributePreferredSharedMemoryCarveout, 100);
    cudaFuncSetAttribute(flash_attn_mma, cudaFuncAttributePreferredSharedMemoryCarveout, 100);

    round_pre<<<(PRE_TOTAL + 255) / 256, 256>>>(q, k, v, wq, wk, wv, wo);

    gemm_qkv<<<dim3(DMODEL / 128, S_LEN / 64, 3), 256, GEMM_SMEM_BYTES>>>(bq, bk, bv);

    flash_attn_mma<<<(S_LEN / 64) * NHEADS, 128, ATTN_SMEM_BYTES>>>();

    gemm_out<<<dim3(DMODEL / 128, S_LEN / 64), 256, GEMM_SMEM_BYTES>>>(bo, out);
}

// round 17
// speedup vs baseline: 1.0204x; 1.0204x over previous
#include <cuda_runtime.h>
#include <cuda_fp16.h>
#include <cstdint>
#include <math.h>

#define S_LEN 4096
#define DMODEL 768
#define NHEADS 12
#define DHEAD 64

// Scratch (static device globals — no allocation allowed)
__device__ __half g_Qh[NHEADS * S_LEN * DHEAD];   // [h][s][d] fp16(0.125*log2e*qproj)
__device__ __half g_Kh[NHEADS * S_LEN * DHEAD];   // [h][s][d] fp16
__device__ __half g_Vh[NHEADS * S_LEN * DHEAD];   // [h][s][d] fp16 (natural)
__device__ __half g_Ctx[S_LEN * DMODEL];          // [s][dmodel] fp16
// fp16 copies of inputs/weights
__device__ __half g_Aq[S_LEN * DMODEL];
__device__ __half g_Ak[S_LEN * DMODEL];
__device__ __half g_Av[S_LEN * DMODEL];
__device__ __half g_Wq[DMODEL * DMODEL];
__device__ __half g_Wk[DMODEL * DMODEL];
__device__ __half g_Wv[DMODEL * DMODEL];
__device__ __half g_Wo[DMODEL * DMODEL];

#define QSCALE 0.1803368801111214f   // 0.125 * log2(e)

// ---------------------------------------------------------------------------
// PTX helpers (sm_80-era PTX only — compute_103 baseline-safe)
// ---------------------------------------------------------------------------
__device__ __forceinline__ uint32_t smem_u32(const void* p) {
    uint32_t a;
    asm("{ .reg .u64 t; cvta.to.shared.u64 t, %1; cvt.u32.u64 %0, t; }"
        : "=r"(a) : "l"(p));
    return a;
}

#define CP_ASYNC16(dst, src) \
    asm volatile("cp.async.cg.shared.global [%0], [%1], 16;" \
                 :: "r"(dst), "l"(src))
#define CP_COMMIT() asm volatile("cp.async.commit_group;" ::: "memory")
#define CP_WAIT3()  asm volatile("cp.async.wait_group 3;" ::: "memory")
#define CP_WAIT2()  asm volatile("cp.async.wait_group 2;" ::: "memory")
#define CP_WAIT0()  asm volatile("cp.async.wait_group 0;" ::: "memory")

__device__ __forceinline__ void ldsm_x4(uint32_t* r, uint32_t addr) {
    asm volatile("ldmatrix.sync.aligned.m8n8.x4.shared.b16 {%0,%1,%2,%3}, [%4];"
                 : "=r"(r[0]), "=r"(r[1]), "=r"(r[2]), "=r"(r[3]) : "r"(addr));
}
__device__ __forceinline__ void ldsm_x4t(uint32_t* r, uint32_t addr) {
    asm volatile("ldmatrix.sync.aligned.m8n8.x4.trans.shared.b16 {%0,%1,%2,%3}, [%4];"
                 : "=r"(r[0]), "=r"(r[1]), "=r"(r[2]), "=r"(r[3]) : "r"(addr));
}
__device__ __forceinline__ void mma_f16(float* c, const uint32_t* a, const uint32_t* b) {
    asm volatile(
        "mma.sync.aligned.m16n8k16.row.col.f32.f16.f16.f32 "
        "{%0,%1,%2,%3}, {%4,%5,%6,%7}, {%8,%9}, {%0,%1,%2,%3};"
        : "+f"(c[0]), "+f"(c[1]), "+f"(c[2]), "+f"(c[3])
        : "r"(a[0]), "r"(a[1]), "r"(a[2]), "r"(a[3]), "r"(b[0]), "r"(b[1]));
}
__device__ __forceinline__ uint32_t packh2(float x, float y) {
    __half2 h = __floats2half2_rn(x, y);
    return *(uint32_t*)&h;
}
__device__ __forceinline__ uint32_t h2exp2u(uint32_t x) {
    uint32_t r;
    asm("ex2.approx.f16x2 %0, %1;" : "=r"(r) : "r"(x));
    return r;
}

// ---------------------------------------------------------------------------
// Pre-convert pass: f32 -> f16 for inputs and weights (memory bound)
// ---------------------------------------------------------------------------
#define NA8 (S_LEN * DMODEL / 8)
#define NW8 (DMODEL * DMODEL / 8)
#define PRE_TOTAL (3 * NA8 + 4 * NW8)

__global__ __launch_bounds__(256)
void round_pre(const float* __restrict__ q, const float* __restrict__ k,
               const float* __restrict__ v,
               const float* __restrict__ wq, const float* __restrict__ wk,
               const float* __restrict__ wv, const float* __restrict__ wo)
{
    int idx = blockIdx.x * 256 + threadIdx.x;
    if (idx >= PRE_TOTAL) return;
    const float* src;
    __half* dst;
    int local;
    if (idx < 3 * NA8) {
        int t = idx / NA8;
        local = idx - t * NA8;
        src = (t == 0) ? q : (t == 1) ? k : v;
        dst = (t == 0) ? g_Aq : (t == 1) ? g_Ak : g_Av;
    } else {
        int j = idx - 3 * NA8;
        int t = j / NW8;
        local = j - t * NW8;
        src = (t == 0) ? wq : (t == 1) ? wk : (t == 2) ? wv : wo;
        dst = (t == 0) ? g_Wq : (t == 1) ? g_Wk : (t == 2) ? g_Wv : g_Wo;
    }
    const float4* s4 = (const float4*)src + local * 2;
    float4 x0 = s4[0], x1 = s4[1];
    uint4 o;
    o.x = packh2(x0.x, x0.y);
    o.y = packh2(x0.z, x0.w);
    o.z = packh2(x1.x, x1.y);
    o.w = packh2(x1.z, x1.w);
    ((uint4*)dst)[local] = o;
}

// ---------------------------------------------------------------------------
// FP16 GEMM 64x128 tile core (round-14 verbatim: BK=32, 24 k-tiles, 256
// threads, 8 warps of 64m x 16n). Rows padded to 80B. 4-stage cp.async,
// 1 barrier/tile.
// ---------------------------------------------------------------------------
#define ROWB 80
#define B_TILE_BYTES (128 * ROWB)
#define A_TILE_BYTES (64 * ROWB)
#define G_STAGE_BYTES (A_TILE_BYTES + B_TILE_BYTES)
#define NSTAGE 4
#define GEMM_SMEM_BYTES (NSTAGE * G_STAGE_BYTES)
#define KT_TILES 24

#define GEMM64_CORE(A_PTR, B_PTR, ACC)                                         \
    extern __shared__ float sm[];                                              \
    const uint32_t sbase = smem_u32(sm);                                       \
    const int tid  = threadIdx.x;                                              \
    const int lane = tid & 31;                                                 \
    const int wid  = tid >> 5;                                                 \
    const int warp_n = wid * 16;                                               \
    const char* gA = (const char*)(A_PTR);                                     \
    const char* gB = (const char*)(B_PTR);                                     \
    auto issue = [&](int kt) {                                                 \
        int stage = kt & (NSTAGE - 1);                                         \
        uint32_t dstBase = sbase + stage * G_STAGE_BYTES;                      \
        _Pragma("unroll")                                                      \
        for (int c = 0; c < 3; c++) {                                          \
            int idx = tid + c * 256;                                           \
            if (idx < 256) {                                                   \
                int row = idx >> 2, ch = idx & 3;                              \
                CP_ASYNC16(dstBase + row * ROWB + ch * 16,                     \
                           gA + (size_t)row * 1536 + (size_t)kt * 64 + ch * 16); \
            } else {                                                           \
                int j = idx - 256;                                             \
                int row = j >> 2, ch = j & 3;                                  \
                CP_ASYNC16(dstBase + A_TILE_BYTES + row * ROWB + ch * 16,      \
                           gB + (size_t)row * 1536 + (size_t)kt * 64 + ch * 16); \
            }                                                                  \
        }                                                                      \
    };                                                                         \
    _Pragma("unroll")                                                          \
    for (int i = 0; i < 4; i++)                                                \
        _Pragma("unroll")                                                      \
        for (int j = 0; j < 2; j++)                                            \
            _Pragma("unroll")                                                  \
            for (int r = 0; r < 4; r++) ACC[i][j][r] = 0.f;                    \
    issue(0); CP_COMMIT();                                                     \
    issue(1); CP_COMMIT();                                                     \
    issue(2); CP_COMMIT();                                                     \
    const int a_row  = lane & 15;                                              \
    const int a_ch   = (lane >> 4) & 1;                                        \
    const int b_row  = lane & 7;                                               \
    const int b_half = (lane >> 3) & 1;                                        \
    const int b_pair = (lane >> 4) & 1;                                        \
    for (int kt = 0; kt < KT_TILES; kt++) {                                    \
        CP_WAIT2();                                                            \
        __syncthreads();                                                       \
        if (kt + 3 < KT_TILES) issue(kt + 3);                                  \
        CP_COMMIT();                                                           \
        uint32_t aS = sbase + (kt & (NSTAGE - 1)) * G_STAGE_BYTES;             \
        uint32_t bS = aS + A_TILE_BYTES;                                       \
        _Pragma("unroll")                                                      \
        for (int ks = 0; ks < 2; ks++) {                                       \
            uint32_t a[4][4], b[2][2];                                         \
            _Pragma("unroll")                                                  \
            for (int am = 0; am < 4; am++)                                     \
                ldsm_x4(a[am], aS + (am * 16 + a_row) * ROWB + ks * 32 + a_ch * 16); \
            {                                                                  \
                uint32_t t4[4];                                                \
                ldsm_x4(t4, bS + (warp_n + b_pair * 8 + b_row) * ROWB          \
                            + ks * 32 + b_half * 16);                          \
                b[0][0] = t4[0]; b[0][1] = t4[1];                              \
                b[1][0] = t4[2]; b[1][1] = t4[3];                              \
            }                                                                  \
            _Pragma("unroll")                                                  \
            for (int am = 0; am < 4; am++)                                     \
                _Pragma("unroll")                                              \
                for (int bn = 0; bn < 2; bn++)                                 \
                    mma_f16(ACC[am][bn], a[am], b[bn]);                        \
        }                                                                      \
    }

// Fused Q/K/V projections, 64x128 tiles. z selects projection.
__global__ __launch_bounds__(256)
void gemm_qkv(const float* __restrict__ bq, const float* __restrict__ bk,
              const float* __restrict__ bv)
{
    const int z = blockIdx.z;
    const __half* A   = (z == 0) ? g_Aq : (z == 1) ? g_Ak : g_Av;
    const __half* W   = (z == 0) ? g_Wq : (z == 1) ? g_Wk : g_Wv;
    const float* bias = (z == 0) ? bq : (z == 1) ? bk : bv;
    const int m0 = blockIdx.y * 64;
    const int n0 = blockIdx.x * 128;

    float acc[4][2][4];
    GEMM64_CORE(A + (size_t)m0 * DMODEL, W + (size_t)n0 * DMODEL, acc)

    const int g   = lane >> 2;
    const int tig = lane & 3;
#pragma unroll
    for (int am = 0; am < 4; am++) {
#pragma unroll
        for (int bn = 0; bn < 2; bn++) {
            int ncol = n0 + warp_n + bn * 8 + tig * 2;
            float2 bz = *(const float2*)(bias + ncol);
            int hd = ncol >> 6;
            int d  = ncol & 63;
            __half* base = (z == 0) ? g_Qh : (z == 1) ? g_Kh : g_Vh;
            float sc = (z == 0) ? QSCALE : 1.f;
#pragma unroll
            for (int h = 0; h < 2; h++) {
                int m = m0 + am * 16 + g + h * 8;
                float ox = (acc[am][bn][h * 2 + 0] + bz.x) * sc;
                float oy = (acc[am][bn][h * 2 + 1] + bz.y) * sc;
                *(uint32_t*)(base + ((size_t)hd * S_LEN + m) * DHEAD + d) =
                    packh2(ox, oy);
            }
        }
    }
}

// Output projection: g_Ctx (fp16) @ g_Wo^T + bo -> fp32 out.
__global__ __launch_bounds__(256)
void gemm_out(const float* __restrict__ bo, float* __restrict__ Out)
{
    const int m0 = blockIdx.y * 64;
    const int n0 = blockIdx.x * 128;

    float acc[4][2][4];
    GEMM64_CORE(g_Ctx + (size_t)m0 * DMODEL, g_Wo + (size_t)n0 * DMODEL, acc)

    const int g   = lane >> 2;
    const int tig = lane & 3;
#pragma unroll
    for (int am = 0; am < 4; am++) {
#pragma unroll
        for (int bn = 0; bn < 2; bn++) {
            int ncol = n0 + warp_n + bn * 8 + tig * 2;
            float2 bz = *(const float2*)(bo + ncol);
#pragma unroll
            for (int h = 0; h < 2; h++) {
                int m = m0 + am * 16 + g + h * 8;
                float2 o;
                o.x = acc[am][bn][h * 2 + 0] + bz.x;
                o.y = acc[am][bn][h * 2 + 1] + bz.y;
                *(float2*)(Out + (size_t)m * DMODEL + ncol) = o;
            }
        }
    }
}

// ---------------------------------------------------------------------------
// FP16 flash attention (causal) — round-14 core + warp-uniform rescale skip:
// when the running max is unchanged across the whole warp (esc==1 exactly),
// skip the o-rescale FMULs and the l FFMA (bit-identical results).
// ---------------------------------------------------------------------------
#define KS_ROWB 144
#define KS_STG  (64 * KS_ROWB)          // 9216
#define OFF_K0  0
#define OFF_K1  (OFF_K0 + KS_STG)
#define OFF_V0  (OFF_K1 + KS_STG)
#define OFF_V1  (OFF_V0 + KS_STG)
#define OFF_Q   (OFF_V1 + KS_STG)
#define ATTN_SMEM_BYTES (OFF_Q + KS_STG)   // 46080

__global__ __launch_bounds__(128, 4)
void flash_attn_mma()
{
    extern __shared__ char smc[];
    const uint32_t sb = smem_u32(smc);
    const int tid  = threadIdx.x;
    const int lane = tid & 31;
    const int w    = tid >> 5;
    // Global LPT ordering: biggest q-blocks first, round-robin across heads.
    const int bid  = blockIdx.x;
    const int head = bid % NHEADS;
    const int qb   = (S_LEN / 64 - 1) - (bid / NHEADS);
    const int q0   = qb * 64;

    const __half* Qg = g_Qh + (size_t)head * S_LEN * DHEAD;
    const __half* Kg = g_Kh + (size_t)head * S_LEN * DHEAD;
    const __half* Vg = g_Vh + (size_t)head * S_LEN * DHEAD;

    const int ntiles = qb + 1;

    // group 1: Q tile (64 rows x 128B)
#pragma unroll
    for (int p = 0; p < 4; p++) {
        int e   = tid + p * 128;
        int row = e >> 3;
        int ch  = e & 7;
        CP_ASYNC16(sb + OFF_Q + row * KS_ROWB + ch * 16,
                   (const char*)Qg + (size_t)(q0 + row) * 128 + ch * 16);
    }
    CP_COMMIT();

    auto issue_K = [&](int t) {
        uint32_t ksB = sb + ((t & 1) ? OFF_K1 : OFF_K0);
        int kv0 = t * 64;
#pragma unroll
        for (int c = 0; c < 4; c++) {
            int j = tid + c * 128;
            int row = j >> 3;
            int ch  = j & 7;
            CP_ASYNC16(ksB + row * KS_ROWB + ch * 16,
                       (const char*)Kg + (size_t)(kv0 + row) * 128 + ch * 16);
        }
    };
    auto issue_V = [&](int t) {
        uint32_t vB = sb + ((t & 1) ? OFF_V1 : OFF_V0);
        int kv0 = t * 64;
#pragma unroll
        for (int c = 0; c < 4; c++) {
            int j = tid + c * 128;
            int row = j >> 3;
            int ch  = j & 7;
            CP_ASYNC16(vB + row * KS_ROWB + ch * 16,
                       (const char*)Vg + (size_t)(kv0 + row) * 128 + ch * 16);
        }
    };

    issue_K(0); CP_COMMIT();                  // group 2
    if (ntiles > 1) issue_K(1);
    CP_COMMIT();                              // group 3
    issue_V(0); CP_COMMIT();                  // group 4

    CP_WAIT3();            // Q done
    __syncthreads();

    const int a_row = lane & 15;
    const int a_ch  = (lane >> 4) & 1;
    const uint32_t aQ = sb + OFF_Q + (w * 16 + a_row) * KS_ROWB + a_ch * 16;

    uint32_t qh[4][4];
#pragma unroll
    for (int kb = 0; kb < 4; kb++)
        ldsm_x4(qh[kb], aQ + kb * 32);

    float m_[2] = {-1e30f, -1e30f};
    float l_[2] = {0.f, 0.f};
    float o[8][4];
#pragma unroll
    for (int nb = 0; nb < 8; nb++)
#pragma unroll
        for (int j = 0; j < 4; j++) o[nb][j] = 0.f;

    CP_WAIT2();            // K0 done
    __syncthreads();

    const int b_nboff = ((lane >> 4) & 1) * 8;
    const int b_row   = lane & 7;
    const int b_half  = (lane >> 3) & 1;
    const int v_row   = lane & 15;
    const int v_hi    = (lane >> 4) & 1;
    const int g       = lane >> 2;
    const int tg      = lane & 3;

    // prologue: S_0 = Q K_0
    float s[8][4];
#pragma unroll
    for (int nb = 0; nb < 8; nb++)
#pragma unroll
        for (int j = 0; j < 4; j++) s[nb][j] = 0.f;
    {
        uint32_t ksS = sb + OFF_K0;
#pragma unroll
        for (int kb = 0; kb < 4; kb++) {
            uint32_t bh[16];
#pragma unroll
            for (int bp = 0; bp < 4; bp++) {
                uint32_t roff = (bp * 16 + b_nboff + b_row) * KS_ROWB + kb * 32 + b_half * 16;
                ldsm_x4(&bh[bp * 4], ksS + roff);
            }
#pragma unroll
            for (int nb = 0; nb < 8; nb++)
                mma_f16(s[nb], qh[kb], &bh[nb * 2]);
        }
    }

    for (int t = 0; t < ntiles; t++) {
        CP_WAIT0();          // K_{t+1}, V_t complete
        __syncthreads();
        if (t + 2 < ntiles) issue_K(t + 2);
        CP_COMMIT();
        if (t + 1 < ntiles) issue_V(t + 1);
        CP_COMMIT();

        const bool do_qk = (t + 1 < ntiles);
        uint32_t ksN = sb + (((t + 1) & 1) ? OFF_K1 : OFF_K0);
        uint32_t vS  = sb + ((t & 1) ? OFF_V1 : OFF_V0);

        // causal mask (diagonal tile only); scores are in log2 domain
        if (t == qb) {
            int kv0 = t * 64;
            int qa = q0 + w * 16 + g;
#pragma unroll
            for (int nb = 0; nb < 8; nb++) {
#pragma unroll
                for (int j = 0; j < 4; j++) {
                    int col = kv0 + nb * 8 + 2 * tg + (j & 1);
                    int row = qa + (j >> 1) * 8;
                    if (col > row) s[nb][j] = -1e30f;
                }
            }
        }

        // online softmax (base-2). pk[r][nb] = packed fp16 probs = PV A-frags.
        uint32_t pk[2][8];
#pragma unroll
        for (int r = 0; r < 2; r++) {
            float mx = m_[r];
#pragma unroll
            for (int nb = 0; nb < 8; nb++)
                mx = fmaxf(mx, fmaxf(s[nb][2 * r], s[nb][2 * r + 1]));
            mx = fmaxf(mx, __shfl_xor_sync(0xffffffffu, mx, 1));
            mx = fmaxf(mx, __shfl_xor_sync(0xffffffffu, mx, 2));
            const bool changed = (mx != m_[r]);
            float sum = 0.f;
#pragma unroll
            for (int nb = 0; nb < 8; nb++) {
                __half2 hx = __floats2half2_rn(s[nb][2 * r] - mx, s[nb][2 * r + 1] - mx);
                uint32_t pe = h2exp2u(*(uint32_t*)&hx);
                pk[r][nb] = pe;
                float2 pf = __half22float2(*(__half2*)&pe);
                sum += pf.x + pf.y;
            }
            sum += __shfl_xor_sync(0xffffffffu, sum, 1);
            sum += __shfl_xor_sync(0xffffffffu, sum, 2);
            // Warp-uniform skip: if no lane's max changed, esc==1 for all
            // lanes -> rescale is an exact identity; skip the FMULs/FFMA.
            if (__any_sync(0xffffffffu, changed)) {
                float esc = exp2f(m_[r] - mx);   // ==1.0 exactly if !changed
                l_[r] = l_[r] * esc + sum;
#pragma unroll
                for (int nb = 0; nb < 8; nb++) {
                    o[nb][2 * r]     *= esc;
                    o[nb][2 * r + 1] *= esc;
                }
            } else {
                l_[r] += sum;
            }
            m_[r] = mx;
        }

        if (do_qk) {
#pragma unroll
            for (int nb = 0; nb < 8; nb++)
#pragma unroll
                for (int j = 0; j < 4; j++) s[nb][j] = 0.f;
        }

        // interleaved: S_{t+1} = Q K_{t+1}  +  O += P_t V_t (register P)
#pragma unroll
        for (int u = 0; u < 4; u++) {
            if (do_qk) {
                uint32_t bh[16];
#pragma unroll
                for (int bp = 0; bp < 4; bp++) {
                    uint32_t roff = (bp * 16 + b_nboff + b_row) * KS_ROWB
                                  + u * 32 + b_half * 16;
                    ldsm_x4(&bh[bp * 4], ksN + roff);
                }
#pragma unroll
                for (int nb = 0; nb < 8; nb++)
                    mma_f16(s[nb], qh[u], &bh[nb * 2]);
            }
            {
                uint32_t pa[4] = {pk[0][2 * u], pk[1][2 * u],
                                  pk[0][2 * u + 1], pk[1][2 * u + 1]};
#pragma unroll
                for (int np = 0; np < 4; np++) {
                    uint32_t t4[4];
                    ldsm_x4t(t4, vS + (u * 16 + v_row) * KS_ROWB
                                 + (2 * np + v_hi) * 16);
                    mma_f16(o[2 * np],     pa, t4);
                    mma_f16(o[2 * np + 1], pa, t4 + 2);
                }
            }
        }
    }

    // epilogue: normalize, write fp16 context [s][dmodel]
#pragma unroll
    for (int r = 0; r < 2; r++) {
        float inv = 1.f / l_[r];
        int qrow = q0 + w * 16 + g + r * 8;
        __half* dst = g_Ctx + (size_t)qrow * DMODEL + head * DHEAD + 2 * tg;
#pragma unroll
        for (int nb = 0; nb < 8; nb++) {
            *(uint32_t*)(dst + nb * 8) =
                packh2(o[nb][2 * r] * inv, o[nb][2 * r + 1] * inv);
        }
    }
}

// ---------------------------------------------------------------------------
extern "C" void kernel_launch(void* const* d_in, const int* in_sizes, int n_in,
                              void* d_out, int out_size)
{
    const float* q  = (const float*)d_in[0];
    const float* k  = (const float*)d_in[1];
    const float* v  = (const float*)d_in[2];
    const float* wq = (const float*)d_in[3];
    const float* bq = (const float*)d_in[4];
    const float* wk = (const float*)d_in[5];
    const float* bk = (const float*)d_in[6];
    const float* wv = (const float*)d_in[7];
    const float* bv = (const float*)d_in[8];
    const float* wo = (const float*)d_in[9];
    const float* bo = (const float*)d_in[10];
    float* out = (float*)d_out;

    cudaFuncSetAttribute(gemm_qkv, cudaFuncAttributeMaxDynamicSharedMemorySize, GEMM_SMEM_BYTES);
    cudaFuncSetAttribute(gemm_out, cudaFuncAttributeMaxDynamicSharedMemorySize, GEMM_SMEM_BYTES);
    cudaFuncSetAttribute(flash_attn_mma, cudaFuncAttributeMaxDynamicSharedMemorySize, ATTN_SMEM_BYTES);

    round_pre<<<(PRE_TOTAL + 255) / 256, 256>>>(q, k, v, wq, wk, wv, wo);

    gemm_qkv<<<dim3(DMODEL / 128, S_LEN / 64, 3), 256, GEMM_SMEM_BYTES>>>(bq, bk, bv);

    flash_attn_mma<<<(S_LEN / 64) * NHEADS, 128, ATTN_SMEM_BYTES>>>();

    gemm_out<<<dim3(DMODEL / 128, S_LEN / 64), 256, GEMM_SMEM_BYTES>>>(bo, out);
}